// round 1
// baseline (speedup 1.0000x reference)
#include <cuda_runtime.h>
#include <math.h>

#define HW 65536            // 256*256
#define NCH 16

// ---------------- device scratch (allocation-free) ----------------
__device__ float g_bufA[2*16*8*HW];          // 64 MB ping
__device__ float g_bufB[2*16*8*HW];          // 64 MB pong
__device__ float g_wrL[8*3*16*49];           // rotated lift weights [m][ci][co][49]
__device__ float g_krot[8*128*16*25];        // rotated gconv weights [m][ci*8+o][co][25]
__device__ float g_w4[128*128];              // orientation-shifted 1x1 weights [p=co*8+m][q=ci*8+o]
__device__ float g_psum[16*64];
__device__ float g_psq[16*64];
__device__ float g_sc[16];
__device__ float g_bi[16];

// ---------------- bilinear kernel rotation ----------------
__device__ __forceinline__ float rot_sample(const float* W, int k, float cs, float sn,
                                            int i, int j) {
    float c  = 0.5f * (float)(k - 1);
    float ys = (float)i - c, xs = (float)j - c;
    float sy = cs * ys - sn * xs + c;
    float sx = sn * ys + cs * xs + c;
    float fy = floorf(sy), fx = floorf(sx);
    int y0 = (int)fy, x0 = (int)fx;
    float wy = sy - fy, wx = sx - fx;
    float v00 = (y0   >= 0 && y0   < k && x0   >= 0 && x0   < k) ? W[y0*k + x0]       : 0.f;
    float v01 = (y0   >= 0 && y0   < k && x0+1 >= 0 && x0+1 < k) ? W[y0*k + x0 + 1]   : 0.f;
    float v10 = (y0+1 >= 0 && y0+1 < k && x0   >= 0 && x0   < k) ? W[(y0+1)*k + x0]   : 0.f;
    float v11 = (y0+1 >= 0 && y0+1 < k && x0+1 >= 0 && x0+1 < k) ? W[(y0+1)*k + x0+1] : 0.f;
    return v00*(1.f-wy)*(1.f-wx) + v01*(1.f-wy)*wx + v10*wy*(1.f-wx) + v11*wy*wx;
}

__global__ void rotate_lift_kernel(const float* __restrict__ lw) {
    int idx = blockIdx.x * 256 + threadIdx.x;
    if (idx >= 8*3*16*49) return;
    int j  = idx % 49;
    int co = (idx / 49) % 16;
    int ci = (idx / (49*16)) % 3;
    int m  = idx / (49*48);
    float th = (float)((double)m * (2.0 * M_PI / 8.0));
    float cs = cosf(th), sn = sinf(th);
    const float* W = lw + (co*3 + ci) * 49;
    g_wrL[((m*3 + ci)*16 + co)*49 + j] = rot_sample(W, 7, cs, sn, j/7, j%7);
}

__global__ void rotate_g_kernel(const float* __restrict__ w) {
    int idx = blockIdx.x * 256 + threadIdx.x;   // grid sized to exactly 409600
    int j    = idx % 25;
    int co   = (idx / 25) % 16;
    int c128 = (idx / 400) % 128;
    int m    = idx / (400*128);
    int ci = c128 >> 3, o = c128 & 7;
    int oo = (o + 8 - m) & 7;                   // (o - m) mod 8
    float th = (float)((double)m * (2.0 * M_PI / 8.0));
    float cs = cosf(th), sn = sinf(th);
    const float* W = w + ((co*16 + ci)*8 + oo) * 25;
    g_krot[idx] = rot_sample(W, 5, cs, sn, j/5, j%5);
}

__global__ void build_w4_kernel(const float* __restrict__ w4) {
    int idx = blockIdx.x * 256 + threadIdx.x;   // 16384
    int q = idx & 127, p = idx >> 7;
    int co = p >> 3, m = p & 7;
    int ci = q >> 3, o = q & 7;
    g_w4[idx] = w4[(co*16 + ci)*8 + ((o + 8 - m) & 7)];
}

// ---------------- lift conv: x[2,3,256,256] (reflect pad 3, 7x7) -> g_bufA[2,16,8,256,256]
__global__ __launch_bounds__(256) void lift_kernel(const float* __restrict__ x) {
    int z = blockIdx.z; int b = z >> 3, m = z & 7;
    int x0 = blockIdx.x * 16, y0 = blockIdx.y * 16;
    int t = threadIdx.x; int tx = t & 15, ty = t >> 4;
    __shared__ float s_in[22*22];
    __shared__ float s_w[16*49];
    float acc[16];
#pragma unroll
    for (int i = 0; i < 16; ++i) acc[i] = 0.f;
#pragma unroll 1
    for (int ci = 0; ci < 3; ++ci) {
        const float* ip = x + (b*3 + ci) * HW;
        for (int idx = t; idx < 484; idx += 256) {
            int iy = idx / 22, ix = idx - iy*22;
            int gy = y0 + iy - 3; gy = gy < 0 ? -gy : (gy > 255 ? 510 - gy : gy);
            int gx = x0 + ix - 3; gx = gx < 0 ? -gx : (gx > 255 ? 510 - gx : gx);
            s_in[idx] = ip[gy*256 + gx];
        }
        const float* wp = g_wrL + (m*3 + ci) * 16 * 49;
        for (int idx = t; idx < 784; idx += 256) s_w[idx] = wp[idx];
        __syncthreads();
        float tap[49];
#pragma unroll
        for (int ky = 0; ky < 7; ++ky)
#pragma unroll
            for (int kx = 0; kx < 7; ++kx)
                tap[ky*7 + kx] = s_in[(ty+ky)*22 + tx + kx];
#pragma unroll
        for (int co = 0; co < 16; ++co) {
            float a = acc[co];
#pragma unroll
            for (int j = 0; j < 49; ++j)
                a = fmaf(tap[j], s_w[co*49 + j], a);
            acc[co] = a;
        }
        __syncthreads();
    }
    int pix = (y0 + ty) * 256 + x0 + tx;
#pragma unroll
    for (int co = 0; co < 16; ++co)
        g_bufA[((b*16 + co)*8 + m)*HW + pix] = acc[co];
}

// ---------------- BN stats: deterministic two-level reduction ----------------
__global__ void stats_partial_kernel(int which) {
    const float* in = which ? g_bufB : g_bufA;
    int c = blockIdx.y, chunk = blockIdx.x, t = threadIdx.x;
    float s = 0.f, ss = 0.f;
    int base = chunk * 16384 + t;
#pragma unroll 4
    for (int k = 0; k < 64; ++k) {
        int e = base + k * 256;
        int b = e >> 19;
        int r = e & ((1 << 19) - 1);
        float v = in[((b*16 + c) << 19) + r];
        s += v; ss += v * v;
    }
    __shared__ float sh1[256], sh2[256];
    sh1[t] = s; sh2[t] = ss;
    __syncthreads();
    for (int off = 128; off > 0; off >>= 1) {
        if (t < off) { sh1[t] += sh1[t + off]; sh2[t] += sh2[t + off]; }
        __syncthreads();
    }
    if (t == 0) { g_psum[c*64 + chunk] = sh1[0]; g_psq[c*64 + chunk] = sh2[0]; }
}

__global__ void stats_final_kernel(const float* __restrict__ g, const float* __restrict__ b) {
    int c = threadIdx.x;
    if (c >= 16) return;
    float s = 0.f, ss = 0.f;
    for (int i = 0; i < 64; ++i) { s += g_psum[c*64 + i]; ss += g_psq[c*64 + i]; }
    const float invN = 1.0f / 1048576.0f;
    float mean = s * invN;
    float var  = ss * invN - mean * mean;
    float sc = g[c] * rsqrtf(var + 1e-5f);
    g_sc[c] = sc;
    g_bi[c] = b[c] - mean * sc;
}

// ---------------- g-conv 5x5 (reflect pad 2), input fused BN+ReLU ----------------
// Each thread: 2x2 pixels x 8 output channels. Block tile 32x32 pixels.
// dir=0: A->B, dir=1: B->A
__global__ __launch_bounds__(256, 2) void gconv_kernel(int dir) {
    const float* in = dir ? g_bufB : g_bufA;
    float* out      = dir ? g_bufA : g_bufB;
    int bz = blockIdx.z;
    int ch = bz & 1;
    int m  = (bz >> 1) & 7;
    int b  = bz >> 4;
    int x0 = blockIdx.x * 32, y0 = blockIdx.y * 32;
    int t = threadIdx.x;
    int lx = (t & 15) * 2, ly = (t >> 4) * 2;
    __shared__ float s_in[36*36];
    __shared__ float s_w[200];
    float acc[8][4];
#pragma unroll
    for (int i = 0; i < 8; ++i) { acc[i][0]=acc[i][1]=acc[i][2]=acc[i][3]=0.f; }
    const float* wbase = g_krot + (size_t)m * 51200 + ch * 200;
#pragma unroll 1
    for (int c128 = 0; c128 < 128; ++c128) {
        int ci = c128 >> 3;
        const float* ip = in + ((b*16 + ci)*8 + (c128 & 7)) * HW;
        float sc = g_sc[ci], bi = g_bi[ci];
        for (int idx = t; idx < 1296; idx += 256) {
            int iy = idx / 36, ix = idx - iy*36;
            int gy = y0 + iy - 2; gy = gy < 0 ? -gy : (gy > 255 ? 510 - gy : gy);
            int gx = x0 + ix - 2; gx = gx < 0 ? -gx : (gx > 255 ? 510 - gx : gx);
            s_in[idx] = fmaxf(fmaf(ip[gy*256 + gx], sc, bi), 0.f);
        }
        if (t < 200) s_w[t] = wbase[c128 * 400 + t];
        __syncthreads();
        float tap[36];
#pragma unroll
        for (int r = 0; r < 6; ++r)
#pragma unroll
            for (int cc = 0; cc < 6; ++cc)
                tap[r*6 + cc] = s_in[(ly + r)*36 + lx + cc];
#pragma unroll
        for (int co = 0; co < 8; ++co) {
#pragma unroll
            for (int ky = 0; ky < 5; ++ky)
#pragma unroll
                for (int kx = 0; kx < 5; ++kx) {
                    float w = s_w[co*25 + ky*5 + kx];
                    acc[co][0] = fmaf(tap[ky*6 + kx],       w, acc[co][0]);
                    acc[co][1] = fmaf(tap[ky*6 + kx + 1],   w, acc[co][1]);
                    acc[co][2] = fmaf(tap[(ky+1)*6 + kx],   w, acc[co][2]);
                    acc[co][3] = fmaf(tap[(ky+1)*6 + kx+1], w, acc[co][3]);
                }
        }
        __syncthreads();
    }
#pragma unroll
    for (int j = 0; j < 8; ++j) {
        int co = ch*8 + j;
        float* op = out + ((b*16 + co)*8 + m) * HW;
        *(float2*)&op[(y0+ly  )*256 + x0 + lx] = make_float2(acc[j][0], acc[j][1]);
        *(float2*)&op[(y0+ly+1)*256 + x0 + lx] = make_float2(acc[j][2], acc[j][3]);
    }
}

// ---------------- conv4: 1x1 orientation-mixing conv (B -> A), fused input BN+ReLU
__global__ __launch_bounds__(256) void conv4_kernel() {
    const float* in = g_bufB;
    float* out = g_bufA;
    int b = blockIdx.y;
    int pix0 = blockIdx.x * 64;
    int t = threadIdx.x;
    int pix = t & 63, pg = t >> 6;
    __shared__ float s_x[512];
    __shared__ float s_w[1024];
    float acc[32];
#pragma unroll
    for (int j = 0; j < 32; ++j) acc[j] = 0.f;
#pragma unroll 1
    for (int qb = 0; qb < 16; ++qb) {
        for (int idx = t; idx < 512; idx += 256) {
            int q8 = idx >> 6, p = idx & 63;
            int q = qb*8 + q8;
            float v = in[(b*128 + q)*HW + pix0 + p];
            s_x[idx] = fmaxf(fmaf(v, g_sc[q >> 3], g_bi[q >> 3]), 0.f);
        }
        for (int idx = t; idx < 1024; idx += 256) {
            int po = idx >> 3, q8 = idx & 7;
            s_w[idx] = g_w4[po*128 + qb*8 + q8];
        }
        __syncthreads();
#pragma unroll
        for (int q8 = 0; q8 < 8; ++q8) {
            float xv = s_x[q8*64 + pix];
#pragma unroll
            for (int j = 0; j < 32; ++j)
                acc[j] = fmaf(xv, s_w[(pg*32 + j)*8 + q8], acc[j]);
        }
        __syncthreads();
    }
#pragma unroll
    for (int j = 0; j < 32; ++j)
        out[(b*128 + pg*32 + j)*HW + pix0 + pix] = acc[j];
}

// ---------------- final: BN4+ReLU, max over orientation, 1x1 + sigmoid ----------------
__global__ void final_kernel(const float* __restrict__ fw, float* __restrict__ out) {
    int gid = blockIdx.x * 256 + threadIdx.x;   // 131072 total
    int b = gid >> 16, pix = gid & 65535;
    float acc = 0.f;
#pragma unroll 1
    for (int co = 0; co < 16; ++co) {
        float sc = g_sc[co], bi = g_bi[co];
        float mv = 0.f;   // relu(v) >= 0, so max over relu == max(0, max v)
#pragma unroll
        for (int m = 0; m < 8; ++m) {
            float v = fmaf(g_bufA[((b*16 + co)*8 + m)*HW + pix], sc, bi);
            mv = fmaxf(mv, v);
        }
        acc = fmaf(fw[co], mv, acc);
    }
    out[gid] = 1.0f / (1.0f + expf(-acc));
}

// ---------------- launch ----------------
extern "C" void kernel_launch(void* const* d_in, const int* in_sizes, int n_in,
                              void* d_out, int out_size) {
    const float* x  = (const float*)d_in[0];
    const float* lw = (const float*)d_in[1];
    const float* w1 = (const float*)d_in[2];
    const float* w2 = (const float*)d_in[3];
    const float* w3 = (const float*)d_in[4];
    const float* w4 = (const float*)d_in[5];
    const float* fw = (const float*)d_in[6];
    const float* g0 = (const float*)d_in[7];  const float* b0 = (const float*)d_in[8];
    const float* g1 = (const float*)d_in[9];  const float* b1 = (const float*)d_in[10];
    const float* g2 = (const float*)d_in[11]; const float* b2 = (const float*)d_in[12];
    const float* g3 = (const float*)d_in[13]; const float* b3 = (const float*)d_in[14];
    const float* g4 = (const float*)d_in[15]; const float* b4 = (const float*)d_in[16];
    float* out = (float*)d_out;

    // lift + BN0 stats
    rotate_lift_kernel<<<74, 256>>>(lw);
    lift_kernel<<<dim3(16,16,16), 256>>>(x);
    stats_partial_kernel<<<dim3(64,16), 256>>>(0);
    stats_final_kernel<<<1, 16>>>(g0, b0);

    // gconv1 (A->B) + BN1 stats
    rotate_g_kernel<<<1600, 256>>>(w1);
    gconv_kernel<<<dim3(8,8,32), 256>>>(0);
    stats_partial_kernel<<<dim3(64,16), 256>>>(1);
    stats_final_kernel<<<1, 16>>>(g1, b1);

    // gconv2 (B->A) + BN2 stats
    rotate_g_kernel<<<1600, 256>>>(w2);
    gconv_kernel<<<dim3(8,8,32), 256>>>(1);
    stats_partial_kernel<<<dim3(64,16), 256>>>(0);
    stats_final_kernel<<<1, 16>>>(g2, b2);

    // gconv3 (A->B) + BN3 stats
    rotate_g_kernel<<<1600, 256>>>(w3);
    gconv_kernel<<<dim3(8,8,32), 256>>>(0);
    stats_partial_kernel<<<dim3(64,16), 256>>>(1);
    stats_final_kernel<<<1, 16>>>(g3, b3);

    // conv4 (B->A) + BN4 stats
    build_w4_kernel<<<64, 256>>>(w4);
    conv4_kernel<<<dim3(1024,2), 256>>>();
    stats_partial_kernel<<<dim3(64,16), 256>>>(0);
    stats_final_kernel<<<1, 16>>>(g4, b4);

    // max-project + final 1x1 + sigmoid
    final_kernel<<<512, 256>>>(fw, out);
}